// round 16
// baseline (speedup 1.0000x reference)
#include <cuda_runtime.h>
#include <cuda_fp16.h>
#include <mma.h>
#include <math.h>
#include <stdint.h>

using namespace nvcuda;

// Problem constants
#define T_TOK 2048
#define H_DIM 1024
#define F_DIM 4096
#define E_NUM 4
#define CAP   2048

#define NTH 256

// ---- gemm1 tiling: 128x128, BK=32, 3-stage, B arrives fp32 + smem convert ----
#define BM 128
#define BN 128
#define BKH1 32
#define LDA1 40                       // A halves stride (BKH1 + 8)
#define LDB  136                      // B halves stride (BN + 8)
#define LDBF 132                      // B fp32 stage stride (BN + 4 floats)
#define LDC  132                      // floats, epilogue staging
// stage layout (bytes): A_h, B_f32, B_h
#define A1_OFF 0
#define BF_OFF (BM * LDA1 * 2)                 // 10240
#define BH_OFF (BF_OFF + BKH1 * LDBF * 4)      // 10240 + 16896 = 27136
#define STG1B  (BH_OFF + BKH1 * LDB * 2)       // 27136 + 8704 = 35840
#define SMEM1  (3 * STG1B)                     // 107520  (>= 128*132*4 epilogue)

// ---- gemm2 tiling (R10 config): 128x128, BK=64, 3-stage, preconverted ----
#define BKH2 64
#define LDA2 72                       // BKH2 + 8 pad
#define STAGES 3
#define STG2 (BM * LDA2 + BKH2 * LDB) // 17920 halves
#define SMEM2 (STAGES * STG2 * (int)sizeof(__half))  // 107520

// gemm2 split-K (KSPLIT=2 is the measured optimum)
#define KSPLIT 2
#define KLEN   (F_DIM / KSPLIT)       // 2048
#define YP_OFF ((size_t)E_NUM * CAP * H_DIM)

// w2 convert chunking (float4 units): 512 tail blocks x 2 chunks
#define W2_CHUNK4  4096
#define W2_NCHUNKS 1024

// ---------------- scratch (static device globals; no allocation) ------------
__device__ __half g_xh[(size_t)T_TOK * H_DIM];
__device__ __half g_w2h[(size_t)E_NUM * F_DIM * H_DIM];
__device__ __half g_act[(size_t)E_NUM * CAP * F_DIM];
__device__ float  g_yp[(size_t)KSPLIT * E_NUM * CAP * H_DIM];   // split-K partials
__device__ int    g_cnt[E_NUM];
__device__ int    g_tok[E_NUM * CAP];
__device__ int    g_slot[T_TOK * E_NUM];

// ---------------- cp.async helpers ------------------------------------------
__device__ __forceinline__ void cp_async16(__half* smem_dst, const __half* gmem_src,
                                           bool pred) {
    unsigned int saddr = (unsigned int)__cvta_generic_to_shared(smem_dst);
    int sz = pred ? 16 : 0;   // src-size 0 -> zero-fill destination
    asm volatile("cp.async.cg.shared.global [%0], [%1], 16, %2;\n"
                 :: "r"(saddr), "l"(gmem_src), "r"(sz));
}
__device__ __forceinline__ void cp_async16g(void* smem_dst, const void* gmem_src) {
    unsigned int saddr = (unsigned int)__cvta_generic_to_shared(smem_dst);
    asm volatile("cp.async.cg.shared.global [%0], [%1], 16;\n"
                 :: "r"(saddr), "l"(gmem_src));
}
#define CP_COMMIT()  asm volatile("cp.async.commit_group;\n" ::)
#define CP_WAIT(n)   asm volatile("cp.async.wait_group %0;\n" :: "n"(n))
#define CP_WAIT0()   asm volatile("cp.async.wait_group 0;\n" ::)

// ---------------- zero counters ----------------------------------------------
__global__ void zero_cnt_kernel() {
    if (threadIdx.x < E_NUM) g_cnt[threadIdx.x] = 0;
}

// ---------------- prep: route (blocks 0..7) + convert x (rest) ---------------
__global__ void prep_kernel(const float* __restrict__ probs,
                            const float* __restrict__ x)
{
    if (blockIdx.x < 8) {
        int t = blockIdx.x * blockDim.x + threadIdx.x;
        if (t >= T_TOK) return;
#pragma unroll
        for (int e = 0; e < E_NUM; e++) {
            float p = probs[t * E_NUM + e];
            if (p > 0.0f) {
                int pos = atomicAdd(&g_cnt[e], 1);
                g_tok[e * CAP + pos] = t;
                g_slot[t * E_NUM + e] = e * CAP + pos;
            }
        }
        return;
    }
    const size_t nx4 = (size_t)T_TOK * H_DIM / 4;   // 524288
    size_t i = (size_t)(blockIdx.x - 8) * blockDim.x + threadIdx.x;
    size_t stride = (size_t)(gridDim.x - 8) * blockDim.x;
    for (; i < nx4; i += stride) {
        float4 v = reinterpret_cast<const float4*>(x)[i];
        reinterpret_cast<__half2*>(g_xh)[i * 2 + 0] = __floats2half2_rn(v.x, v.y);
        reinterpret_cast<__half2*>(g_xh)[i * 2 + 1] = __floats2half2_rn(v.z, v.w);
    }
}

// ---------------- MMA cores ---------------------------------------------------
// 8 warps: warp_m = w>>1 (4 rows of 32), warp_n = w&1 (2 cols of 64)
struct Frags {
    wmma::fragment<wmma::accumulator, 16, 16, 16, float> acc[2][4];
};

__device__ __forceinline__ void mma_stage1(const __half* sA, const __half* sB,
                                           int warp_m, int warp_n, Frags& fr) {
#pragma unroll
    for (int kk = 0; kk < BKH1; kk += 16) {
        wmma::fragment<wmma::matrix_a, 16, 16, 16, __half, wmma::row_major> a[2];
        wmma::fragment<wmma::matrix_b, 16, 16, 16, __half, wmma::row_major> b[4];
#pragma unroll
        for (int i = 0; i < 2; i++)
            wmma::load_matrix_sync(a[i], &sA[(warp_m * 32 + i * 16) * LDA1 + kk], LDA1);
#pragma unroll
        for (int j = 0; j < 4; j++)
            wmma::load_matrix_sync(b[j], &sB[kk * LDB + warp_n * 64 + j * 16], LDB);
#pragma unroll
        for (int i = 0; i < 2; i++)
#pragma unroll
            for (int j = 0; j < 4; j++)
                wmma::mma_sync(fr.acc[i][j], a[i], b[j], fr.acc[i][j]);
    }
}

__device__ __forceinline__ void mma_stage2(const __half* sA, const __half* sB,
                                           int warp_m, int warp_n, Frags& fr) {
#pragma unroll
    for (int kk = 0; kk < BKH2; kk += 16) {
        wmma::fragment<wmma::matrix_a, 16, 16, 16, __half, wmma::row_major> a[2];
        wmma::fragment<wmma::matrix_b, 16, 16, 16, __half, wmma::row_major> b[4];
#pragma unroll
        for (int i = 0; i < 2; i++)
            wmma::load_matrix_sync(a[i], &sA[(warp_m * 32 + i * 16) * LDA2 + kk], LDA2);
#pragma unroll
        for (int j = 0; j < 4; j++)
            wmma::load_matrix_sync(b[j], &sB[kk * LDB + warp_n * 64 + j * 16], LDB);
#pragma unroll
        for (int i = 0; i < 2; i++)
#pragma unroll
            for (int j = 0; j < 4; j++)
                wmma::mma_sync(fr.acc[i][j], a[i], b[j], fr.acc[i][j]);
    }
}

// ---------------- GEMM1: act = gelu( gather(Xh) @ w1 ) -----------------------
// grid: (32, 16, E+1). z<E: GEMM plane (B fp32 via cp.async, smem convert).
// z==E: w2 converter plane (512 blocks, scheduled LAST -> drain-wave only).
__global__ __launch_bounds__(NTH, 2) void gemm1_kernel(
    const float* __restrict__ W1, const float* __restrict__ W2)
{
    extern __shared__ __align__(16) char smem1[];
    const int tid = threadIdx.x;

    if (blockIdx.z == E_NUM) {
        // tail converter plane: 512 blocks x 2 fixed chunks, deterministic
        const float4* src = reinterpret_cast<const float4*>(W2);
        int bid = blockIdx.y * 32 + blockIdx.x;        // 0..511
#pragma unroll
        for (int c = bid * 2; c < bid * 2 + 2; c++) {
            size_t base = (size_t)c * W2_CHUNK4;
#pragma unroll 4
            for (int j = tid; j < W2_CHUNK4; j += NTH) {
                float4 v = src[base + j];
                __half2* d = reinterpret_cast<__half2*>(&g_w2h[(base + j) * 4]);
                d[0] = __floats2half2_rn(v.x, v.y);
                d[1] = __floats2half2_rn(v.z, v.w);
            }
        }
        return;
    }

    const int e   = blockIdx.z;
    const int cnt = g_cnt[e];
    const int m0  = blockIdx.y * BM;
    if (m0 >= cnt) return;
    const int n0  = blockIdx.x * BN;
    const int w   = tid >> 5;
    const int warp_m = w >> 1;
    const int warp_n = w & 1;

    // A tile: 128 rows x 32 halves = 4 chunks(16B)/row, 512 chunks, 2/thread
    int a_row[2], a_col[2], a_tok[2];
    bool a_ok[2];
#pragma unroll
    for (int i = 0; i < 2; i++) {
        int id = tid + i * NTH;
        a_row[i] = id >> 2;
        a_col[i] = (id & 3) * 8;          // half offset
        int m = m0 + a_row[i];
        a_ok[i] = (m < cnt);
        a_tok[i] = a_ok[i] ? __ldg(&g_tok[e * CAP + m]) : 0;
    }
    // B fp32 tile: 32 rows x 128 floats = 1024 16B chunks, 4/thread
    int b_row[4], b_c4[4];
#pragma unroll
    for (int i = 0; i < 4; i++) {
        int id = tid + i * NTH;
        b_row[i] = id >> 5;
        b_c4[i]  = (id & 31) * 4;
    }
    const float* W1e = &W1[(size_t)e * H_DIM * F_DIM];

    Frags fr;
#pragma unroll
    for (int i = 0; i < 2; i++)
#pragma unroll
        for (int j = 0; j < 4; j++) wmma::fill_fragment(fr.acc[i][j], 0.0f);

    const int NK = H_DIM / BKH1;   // 32

    // prologue: issue stages 0 and 1 (A half cp.async + B fp32 cp.async)
#pragma unroll
    for (int s = 0; s < 2; s++) {
        char* st = smem1 + s * STG1B;
        __half* sA = reinterpret_cast<__half*>(st + A1_OFF);
        float*  sBf = reinterpret_cast<float*>(st + BF_OFF);
        const int k0 = s * BKH1;
#pragma unroll
        for (int i = 0; i < 2; i++)
            cp_async16(&sA[a_row[i] * LDA1 + a_col[i]],
                       &g_xh[(size_t)a_tok[i] * H_DIM + k0 + a_col[i]], a_ok[i]);
#pragma unroll
        for (int i = 0; i < 4; i++)
            cp_async16g(&sBf[b_row[i] * LDBF + b_c4[i]],
                        &W1e[(size_t)(k0 + b_row[i]) * F_DIM + n0 + b_c4[i]]);
        CP_COMMIT();
    }

    int buf = 0, nbuf = 2;
#pragma unroll 1
    for (int kt = 0; kt < NK; kt++) {
        CP_WAIT(1);            // stage kt fully arrived
        __syncthreads();       // cp.async writes visible; nbuf's old readers done
        if (kt + 2 < NK) {
            char* st = smem1 + nbuf * STG1B;
            __half* sA = reinterpret_cast<__half*>(st + A1_OFF);
            float*  sBf = reinterpret_cast<float*>(st + BF_OFF);
            const int k0 = (kt + 2) * BKH1;
#pragma unroll
            for (int i = 0; i < 2; i++)
                cp_async16(&sA[a_row[i] * LDA1 + a_col[i]],
                           &g_xh[(size_t)a_tok[i] * H_DIM + k0 + a_col[i]], a_ok[i]);
#pragma unroll
            for (int i = 0; i < 4; i++)
                cp_async16g(&sBf[b_row[i] * LDBF + b_c4[i]],
                            &W1e[(size_t)(k0 + b_row[i]) * F_DIM + n0 + b_c4[i]]);
        }
        CP_COMMIT();           // unconditional: keeps group count aligned

        // convert B fp32 -> half in smem for stage kt
        char* cst = smem1 + buf * STG1B;
        float*  sBf = reinterpret_cast<float*>(cst + BF_OFF);
        __half* sBh = reinterpret_cast<__half*>(cst + BH_OFF);
#pragma unroll
        for (int i = 0; i < 4; i++) {
            float4 v = *reinterpret_cast<const float4*>(&sBf[b_row[i] * LDBF + b_c4[i]]);
            __half2* d = reinterpret_cast<__half2*>(&sBh[b_row[i] * LDB + b_c4[i]]);
            d[0] = __floats2half2_rn(v.x, v.y);
            d[1] = __floats2half2_rn(v.z, v.w);
        }
        __syncthreads();       // converted B visible to all warps

        mma_stage1(reinterpret_cast<__half*>(cst + A1_OFF), sBh, warp_m, warp_n, fr);
        buf  = (buf  == 2) ? 0 : buf + 1;
        nbuf = (nbuf == 2) ? 0 : nbuf + 1;
    }
    CP_WAIT0();
    __syncthreads();

    // epilogue: stage C (float) in smem, gelu, convert to half, store
    float* sC = reinterpret_cast<float*>(smem1);
#pragma unroll
    for (int i = 0; i < 2; i++)
#pragma unroll
        for (int j = 0; j < 4; j++)
            wmma::store_matrix_sync(
                &sC[(warp_m * 32 + i * 16) * LDC + warp_n * 64 + j * 16],
                fr.acc[i][j], LDC, wmma::mem_row_major);
    __syncthreads();
#pragma unroll
    for (int i = 0; i < 16; i++) {       // 4096 4-elem groups / 256 threads
        int id  = tid + i * NTH;
        int row = id >> 5;
        int c   = (id & 31) * 4;
        int m   = m0 + row;
        if (m < cnt) {
            float4 v = *reinterpret_cast<const float4*>(&sC[row * LDC + c]);
            v.x = 0.5f * v.x * (1.0f + erff(v.x * 0.70710678118654752f));
            v.y = 0.5f * v.y * (1.0f + erff(v.y * 0.70710678118654752f));
            v.z = 0.5f * v.z * (1.0f + erff(v.z * 0.70710678118654752f));
            v.w = 0.5f * v.w * (1.0f + erff(v.w * 0.70710678118654752f));
            __half2* dst = reinterpret_cast<__half2*>(
                &g_act[(size_t)(e * CAP + m) * F_DIM + n0 + c]);
            dst[0] = __floats2half2_rn(v.x, v.y);
            dst[1] = __floats2half2_rn(v.z, v.w);
        }
    }
}

// ---------------- GEMM2: yp[half] = act_h[:, half] @ w2h[half] ---------------
// grid: (H/BN=8, CAP/BM=16, E*KSPLIT=8), block: 256
__global__ __launch_bounds__(NTH, 2) void gemm2_kernel()
{
    extern __shared__ __align__(16) __half smem[];
    const int e    = blockIdx.z >> 1;
    const int spl  = blockIdx.z & 1;
    const int cnt  = g_cnt[e];
    const int m0   = blockIdx.y * BM;
    if (m0 >= cnt) return;
    const int n0   = blockIdx.x * BN;
    const int tid  = threadIdx.x;
    const int w    = tid >> 5;
    const int warp_m = w >> 1;
    const int warp_n = w & 1;
    const int kbase = spl * KLEN;

    int a_row[4], a_col[4], b_row[4], b_col[4];
#pragma unroll
    for (int i = 0; i < 4; i++) {
        int id = tid + i * NTH;
        a_row[i] = id >> 3;
        a_col[i] = (id & 7) * 8;
        b_row[i] = id >> 4;
        b_col[i] = (id & 15) * 8;
    }

    const __half* A   = &g_act[(size_t)(e * CAP) * F_DIM];  // stale rows>=cnt unread
    const __half* W2e = &g_w2h[(size_t)e * F_DIM * H_DIM];

    Frags fr;
#pragma unroll
    for (int i = 0; i < 2; i++)
#pragma unroll
        for (int j = 0; j < 4; j++) wmma::fill_fragment(fr.acc[i][j], 0.0f);

    const int NK = KLEN / BKH2;   // 32

#pragma unroll
    for (int s = 0; s < STAGES - 1; s++) {
        __half* sA = smem + s * STG2;
        __half* sB = sA + BM * LDA2;
        const int k0 = kbase + s * BKH2;
#pragma unroll
        for (int i = 0; i < 4; i++)
            cp_async16(&sA[a_row[i] * LDA2 + a_col[i]],
                       &A[(size_t)(m0 + a_row[i]) * F_DIM + k0 + a_col[i]], true);
#pragma unroll
        for (int i = 0; i < 4; i++)
            cp_async16(&sB[b_row[i] * LDB + b_col[i]],
                       &W2e[(size_t)(k0 + b_row[i]) * H_DIM + n0 + b_col[i]], true);
        CP_COMMIT();
    }

    int buf = 0, nbuf = STAGES - 1;
    for (int kt = 0; kt < NK; kt++) {
        CP_WAIT(1);
        __syncthreads();
        if (kt + 2 < NK) {
            __half* sA = smem + nbuf * STG2;
            __half* sB = sA + BM * LDA2;
            const int k0 = kbase + (kt + 2) * BKH2;
#pragma unroll
            for (int i = 0; i < 4; i++)
                cp_async16(&sA[a_row[i] * LDA2 + a_col[i]],
                           &A[(size_t)(m0 + a_row[i]) * F_DIM + k0 + a_col[i]], true);
#pragma unroll
            for (int i = 0; i < 4; i++)
                cp_async16(&sB[b_row[i] * LDB + b_col[i]],
                           &W2e[(size_t)(k0 + b_row[i]) * H_DIM + n0 + b_col[i]], true);
        }
        CP_COMMIT();
        mma_stage2(smem + buf * STG2, smem + buf * STG2 + BM * LDA2,
                   warp_m, warp_n, fr);
        buf  = (buf  == STAGES - 1) ? 0 : buf + 1;
        nbuf = (nbuf == STAGES - 1) ? 0 : nbuf + 1;
    }
    CP_WAIT0();

    // epilogue: store accumulators to this split's partial buffer
    float* yp = g_yp + (size_t)spl * YP_OFF;
#pragma unroll
    for (int i = 0; i < 2; i++)
#pragma unroll
        for (int j = 0; j < 4; j++)
            wmma::store_matrix_sync(
                &yp[(size_t)(e * CAP + m0 + warp_m * 32 + i * 16) * H_DIM
                    + n0 + warp_n * 64 + j * 16],
                fr.acc[i][j], H_DIM, wmma::mem_row_major);
}

// ---------------- combine: out = residual + sum_e p * (yp0 + yp1) -----------
__global__ void combine_kernel(const float* __restrict__ res,
                               const float* __restrict__ probs,
                               float* __restrict__ out)
{
    int t = blockIdx.x;
    int h = threadIdx.x * 4;
    float4 acc = *reinterpret_cast<const float4*>(&res[(size_t)t * H_DIM + h]);
#pragma unroll
    for (int e = 0; e < E_NUM; e++) {
        float p = probs[t * E_NUM + e];
        if (p > 0.0f) {
            int s = g_slot[t * E_NUM + e];
            float4 y0 = *reinterpret_cast<const float4*>(&g_yp[(size_t)s * H_DIM + h]);
            float4 y1 = *reinterpret_cast<const float4*>(
                &g_yp[YP_OFF + (size_t)s * H_DIM + h]);
            acc.x += p * (y0.x + y1.x);
            acc.y += p * (y0.y + y1.y);
            acc.z += p * (y0.z + y1.z);
            acc.w += p * (y0.w + y1.w);
        }
    }
    *reinterpret_cast<float4*>(&out[(size_t)t * H_DIM + h]) = acc;
}

// ---------------- launcher ---------------------------------------------------
extern "C" void kernel_launch(void* const* d_in, const int* in_sizes, int n_in,
                              void* d_out, int out_size)
{
    const float* x     = (const float*)d_in[0];
    const float* res   = (const float*)d_in[1];
    const float* probs = (const float*)d_in[2];
    const float* w1    = (const float*)d_in[4];
    const float* w2    = (const float*)d_in[5];
    float* out = (float*)d_out;

    (void)cudaFuncSetAttribute(gemm1_kernel,
                               cudaFuncAttributeMaxDynamicSharedMemorySize, SMEM1);
    (void)cudaFuncSetAttribute(gemm2_kernel,
                               cudaFuncAttributeMaxDynamicSharedMemorySize, SMEM2);

    zero_cnt_kernel<<<1, 32>>>();
    prep_kernel<<<8 + 128, NTH>>>(probs, x);
    gemm1_kernel<<<dim3(F_DIM / BN, CAP / BM, E_NUM + 1), NTH, SMEM1>>>(w1, w2);
    gemm2_kernel<<<dim3(H_DIM / BN, CAP / BM, E_NUM * KSPLIT), NTH, SMEM2>>>();
    combine_kernel<<<T_TOK, NTH>>>(res, probs, out);
}

// round 17
// speedup vs baseline: 1.0900x; 1.0900x over previous
#include <cuda_runtime.h>
#include <cuda_fp16.h>
#include <mma.h>
#include <math.h>
#include <stdint.h>

using namespace nvcuda;

// Problem constants
#define T_TOK 2048
#define H_DIM 1024
#define F_DIM 4096
#define E_NUM 4
#define CAP   2048

#define NTH 256
#define GTH 128     // gemm2 threads (4 warps)

// ---- gemm1 tiling (R9 config): 128x128, BK=32, 2-stage, inline fp32 B ----
#define BM 128
#define BN 128
#define BKH1 32
#define LDA1 40                       // BKH1 + 8 pad
#define LDB 136                       // BN + 8 pad
#define LDC 132                       // floats, epilogue staging
#define A1_HALFS (BM * LDA1)          // 5120
#define STG1 (BM * LDA1 + BKH1 * LDB) // 9472
#define SMEM1 67584                   // max(2*STG1*2, 128*132*4)

// ---- gemm2 tiling (R11 config): 128x128 CTA, 4 warps of 64x64, BK=64, 3-stage
#define BKH2 64
#define LDA2 72                       // BKH2 + 8 pad
#define STAGES 3
#define STG2 (BM * LDA2 + BKH2 * LDB) // 17920 halves
#define SMEM2 (STAGES * STG2 * (int)sizeof(__half))  // 107520

// gemm2 split-K (KSPLIT=2 is the measured optimum)
#define KSPLIT 2
#define KLEN   (F_DIM / KSPLIT)       // 2048
#define YP_OFF ((size_t)E_NUM * CAP * H_DIM)

// w2 convert chunking (float4 units): 512 tail blocks x 2 chunks
#define W2_CHUNK4  4096
#define W2_NCHUNKS 1024

// ---------------- scratch (static device globals; no allocation) ------------
__device__ __half g_xh[(size_t)T_TOK * H_DIM];
__device__ __half g_w2h[(size_t)E_NUM * F_DIM * H_DIM];
__device__ __half g_act[(size_t)E_NUM * CAP * F_DIM];
__device__ float  g_yp[(size_t)KSPLIT * E_NUM * CAP * H_DIM];   // split-K partials
__device__ int    g_cnt[E_NUM];
__device__ int    g_tok[E_NUM * CAP];
__device__ int    g_slot[T_TOK * E_NUM];

// ---------------- cp.async helpers ------------------------------------------
__device__ __forceinline__ void cp_async16(__half* smem_dst, const __half* gmem_src,
                                           bool pred) {
    unsigned int saddr = (unsigned int)__cvta_generic_to_shared(smem_dst);
    int sz = pred ? 16 : 0;   // src-size 0 -> zero-fill destination
    asm volatile("cp.async.cg.shared.global [%0], [%1], 16, %2;\n"
                 :: "r"(saddr), "l"(gmem_src), "r"(sz));
}
#define CP_COMMIT()  asm volatile("cp.async.commit_group;\n" ::)
#define CP_WAIT(n)   asm volatile("cp.async.wait_group %0;\n" :: "n"(n))
#define CP_WAIT0()   asm volatile("cp.async.wait_group 0;\n" ::)

// ---------------- zero counters ----------------------------------------------
__global__ void zero_cnt_kernel() {
    if (threadIdx.x < E_NUM) g_cnt[threadIdx.x] = 0;
}

// ---------------- prep: route (blocks 0..7) + convert x (rest) ---------------
__global__ void prep_kernel(const float* __restrict__ probs,
                            const float* __restrict__ x)
{
    if (blockIdx.x < 8) {
        int t = blockIdx.x * blockDim.x + threadIdx.x;
        if (t >= T_TOK) return;
#pragma unroll
        for (int e = 0; e < E_NUM; e++) {
            float p = probs[t * E_NUM + e];
            if (p > 0.0f) {
                int pos = atomicAdd(&g_cnt[e], 1);
                g_tok[e * CAP + pos] = t;
                g_slot[t * E_NUM + e] = e * CAP + pos;
            }
        }
        return;
    }
    const size_t nx4 = (size_t)T_TOK * H_DIM / 4;   // 524288
    size_t i = (size_t)(blockIdx.x - 8) * blockDim.x + threadIdx.x;
    size_t stride = (size_t)(gridDim.x - 8) * blockDim.x;
    for (; i < nx4; i += stride) {
        float4 v = reinterpret_cast<const float4*>(x)[i];
        reinterpret_cast<__half2*>(g_xh)[i * 2 + 0] = __floats2half2_rn(v.x, v.y);
        reinterpret_cast<__half2*>(g_xh)[i * 2 + 1] = __floats2half2_rn(v.z, v.w);
    }
}

// ---------------- MMA cores ---------------------------------------------------
// gemm1: 8 warps, warp_m = w>>1 (4 rows of 32), warp_n = w&1 (2 cols of 64)
struct Frags {
    wmma::fragment<wmma::accumulator, 16, 16, 16, float> acc[2][4];
};

__device__ __forceinline__ void mma_stage1(const __half* sA, const __half* sB,
                                           int warp_m, int warp_n, Frags& fr) {
#pragma unroll
    for (int kk = 0; kk < BKH1; kk += 16) {
        wmma::fragment<wmma::matrix_a, 16, 16, 16, __half, wmma::row_major> a[2];
        wmma::fragment<wmma::matrix_b, 16, 16, 16, __half, wmma::row_major> b[4];
#pragma unroll
        for (int i = 0; i < 2; i++)
            wmma::load_matrix_sync(a[i], &sA[(warp_m * 32 + i * 16) * LDA1 + kk], LDA1);
#pragma unroll
        for (int j = 0; j < 4; j++)
            wmma::load_matrix_sync(b[j], &sB[kk * LDB + warp_n * 64 + j * 16], LDB);
#pragma unroll
        for (int i = 0; i < 2; i++)
#pragma unroll
            for (int j = 0; j < 4; j++)
                wmma::mma_sync(fr.acc[i][j], a[i], b[j], fr.acc[i][j]);
    }
}

// gemm2: 4 warps in 2x2, each owns 64x64 (4x4 fragments)
struct Frags4 {
    wmma::fragment<wmma::accumulator, 16, 16, 16, float> acc[4][4];
};

__device__ __forceinline__ void mma_stage2(const __half* sA, const __half* sB,
                                           int warp_m, int warp_n, Frags4& fr) {
#pragma unroll
    for (int kk = 0; kk < BKH2; kk += 16) {
        wmma::fragment<wmma::matrix_a, 16, 16, 16, __half, wmma::row_major> a[4];
#pragma unroll
        for (int i = 0; i < 4; i++)
            wmma::load_matrix_sync(a[i], &sA[(warp_m * 64 + i * 16) * LDA2 + kk], LDA2);
#pragma unroll
        for (int j = 0; j < 4; j++) {
            wmma::fragment<wmma::matrix_b, 16, 16, 16, __half, wmma::row_major> b;
            wmma::load_matrix_sync(b, &sB[kk * LDB + warp_n * 64 + j * 16], LDB);
#pragma unroll
            for (int i = 0; i < 4; i++)
                wmma::mma_sync(fr.acc[i][j], a[i], b, fr.acc[i][j]);
        }
    }
}

// ---------------- B loader for gemm1: fp32 gmem -> regs -> cvt -> smem half ---
__device__ __forceinline__ void ldg_b(float4* r, const float* __restrict__ W,
                                      int ldw, int n0, int k0, int tid) {
#pragma unroll
    for (int i = 0; i < 4; i++) {
        int id  = tid + i * NTH;
        int row = id >> 5;
        int c4  = (id & 31) * 4;
        r[i] = *reinterpret_cast<const float4*>(&W[(size_t)(k0 + row) * ldw + n0 + c4]);
    }
}
__device__ __forceinline__ void sts_b(__half* sB, const float4* r, int tid) {
#pragma unroll
    for (int i = 0; i < 4; i++) {
        int id  = tid + i * NTH;
        int row = id >> 5;
        int c4  = (id & 31) * 4;
        __half2* d = reinterpret_cast<__half2*>(&sB[row * LDB + c4]);
        d[0] = __floats2half2_rn(r[i].x, r[i].y);
        d[1] = __floats2half2_rn(r[i].z, r[i].w);
    }
}

// ---------------- GEMM1: act = gelu( gather(Xh) @ w1 ) -----------------------
// grid: (32, 16, E+1). z<E: GEMM plane. z==E: w2 converter plane (512 blocks,
// scheduled LAST -> runs only in gemm1's drain wave, fixed chunk assignment).
__global__ __launch_bounds__(NTH, 2) void gemm1_kernel(
    const float* __restrict__ W1, const float* __restrict__ W2)
{
    extern __shared__ __align__(16) __half smem[];
    const int tid = threadIdx.x;

    if (blockIdx.z == E_NUM) {
        // tail converter plane: 512 blocks x 2 fixed chunks, deterministic
        const float4* src = reinterpret_cast<const float4*>(W2);
        int bid = blockIdx.y * 32 + blockIdx.x;        // 0..511
#pragma unroll
        for (int c = bid * 2; c < bid * 2 + 2; c++) {
            size_t base = (size_t)c * W2_CHUNK4;
#pragma unroll 4
            for (int j = tid; j < W2_CHUNK4; j += NTH) {
                float4 v = src[base + j];
                __half2* d = reinterpret_cast<__half2*>(&g_w2h[(base + j) * 4]);
                d[0] = __floats2half2_rn(v.x, v.y);
                d[1] = __floats2half2_rn(v.z, v.w);
            }
        }
        return;
    }

    const int e   = blockIdx.z;
    const int cnt = g_cnt[e];
    const int m0  = blockIdx.y * BM;
    if (m0 >= cnt) return;
    const int n0  = blockIdx.x * BN;
    const int w   = tid >> 5;
    const int warp_m = w >> 1;
    const int warp_n = w & 1;

    // A tile: 128 rows x 32 halves = 4 chunks(16B)/row, 512 chunks, 2/thread
    int a_row[2], a_col[2], a_tok[2];
    bool a_ok[2];
#pragma unroll
    for (int i = 0; i < 2; i++) {
        int id = tid + i * NTH;
        a_row[i] = id >> 2;
        a_col[i] = (id & 3) * 8;          // half offset
        int m = m0 + a_row[i];
        a_ok[i] = (m < cnt);
        a_tok[i] = a_ok[i] ? __ldg(&g_tok[e * CAP + m]) : 0;
    }
    const float* W1e = &W1[(size_t)e * H_DIM * F_DIM];

    Frags fr;
#pragma unroll
    for (int i = 0; i < 2; i++)
#pragma unroll
        for (int j = 0; j < 4; j++) wmma::fill_fragment(fr.acc[i][j], 0.0f);

    const int NK = H_DIM / BKH1;   // 32
    float4 regsB[4];

    // prologue
    {
        __half* sA0 = smem;
        __half* sB0 = smem + A1_HALFS;
        ldg_b(regsB, W1e, F_DIM, n0, 0, tid);
        sts_b(sB0, regsB, tid);
#pragma unroll
        for (int i = 0; i < 2; i++)
            cp_async16(&sA0[a_row[i] * LDA1 + a_col[i]],
                       &g_xh[(size_t)a_tok[i] * H_DIM + a_col[i]], a_ok[i]);
        CP_COMMIT();
        __half* sA1 = smem + STG1;
#pragma unroll
        for (int i = 0; i < 2; i++)
            cp_async16(&sA1[a_row[i] * LDA1 + a_col[i]],
                       &g_xh[(size_t)a_tok[i] * H_DIM + BKH1 + a_col[i]], a_ok[i]);
        CP_COMMIT();
        ldg_b(regsB, W1e, F_DIM, n0, BKH1, tid);
        asm volatile("cp.async.wait_group 1;\n" ::);
        __syncthreads();
    }

#pragma unroll 1
    for (int kt = 0; kt < NK; kt++) {
        __half* cur   = smem + (kt & 1) * STG1;
        __half* other = smem + ((kt & 1) ^ 1) * STG1;
        if (kt + 1 < NK) sts_b(other + A1_HALFS, regsB, tid);      // B[kt+1]
        if (kt + 2 < NK) ldg_b(regsB, W1e, F_DIM, n0, (kt + 2) * BKH1, tid);
        mma_stage1(cur, cur + A1_HALFS, warp_m, warp_n, fr);
        CP_WAIT0();           // drain A[kt+1] (only group in flight)
        __syncthreads();
        if (kt + 2 < NK) {
            const int k0 = (kt + 2) * BKH1;
#pragma unroll
            for (int i = 0; i < 2; i++)
                cp_async16(&cur[a_row[i] * LDA1 + a_col[i]],
                           &g_xh[(size_t)a_tok[i] * H_DIM + k0 + a_col[i]], a_ok[i]);
            CP_COMMIT();
        }
    }

    // epilogue: stage C (float) in smem, gelu, convert to half, store
    float* sC = reinterpret_cast<float*>(smem);
#pragma unroll
    for (int i = 0; i < 2; i++)
#pragma unroll
        for (int j = 0; j < 4; j++)
            wmma::store_matrix_sync(
                &sC[(warp_m * 32 + i * 16) * LDC + warp_n * 64 + j * 16],
                fr.acc[i][j], LDC, wmma::mem_row_major);
    __syncthreads();
#pragma unroll
    for (int i = 0; i < 16; i++) {       // 4096 4-elem groups / 256 threads
        int id  = tid + i * NTH;
        int row = id >> 5;
        int c   = (id & 31) * 4;
        int m   = m0 + row;
        if (m < cnt) {
            float4 v = *reinterpret_cast<const float4*>(&sC[row * LDC + c]);
            v.x = 0.5f * v.x * (1.0f + erff(v.x * 0.70710678118654752f));
            v.y = 0.5f * v.y * (1.0f + erff(v.y * 0.70710678118654752f));
            v.z = 0.5f * v.z * (1.0f + erff(v.z * 0.70710678118654752f));
            v.w = 0.5f * v.w * (1.0f + erff(v.w * 0.70710678118654752f));
            __half2* dst = reinterpret_cast<__half2*>(
                &g_act[(size_t)(e * CAP + m) * F_DIM + n0 + c]);
            dst[0] = __floats2half2_rn(v.x, v.y);
            dst[1] = __floats2half2_rn(v.z, v.w);
        }
    }
}

// ---------------- GEMM2 (R11 4-warp core): yp[spl] = act_h @ w2h -------------
// grid: (H/BN=8, CAP/BM=16, E*KSPLIT=8), block: 128
__global__ __launch_bounds__(GTH, 2) void gemm2_kernel()
{
    extern __shared__ __align__(16) __half smem[];
    const int e    = blockIdx.z >> 1;
    const int spl  = blockIdx.z & 1;
    const int cnt  = g_cnt[e];
    const int m0   = blockIdx.y * BM;
    if (m0 >= cnt) return;
    const int n0   = blockIdx.x * BN;
    const int tid  = threadIdx.x;
    const int w    = tid >> 5;
    const int warp_m = w >> 1;
    const int warp_n = w & 1;
    const int kbase = spl * KLEN;

    const __half* A   = &g_act[(size_t)(e * CAP) * F_DIM];  // stale rows>=cnt unread
    const __half* W2e = &g_w2h[(size_t)e * F_DIM * H_DIM];

    Frags4 fr;
#pragma unroll
    for (int i = 0; i < 4; i++)
#pragma unroll
        for (int j = 0; j < 4; j++) wmma::fill_fragment(fr.acc[i][j], 0.0f);

    const int NK = KLEN / BKH2;   // 32

#pragma unroll
    for (int s = 0; s < STAGES - 1; s++) {
        __half* sA = smem + s * STG2;
        __half* sB = sA + BM * LDA2;
        const int k0 = kbase + s * BKH2;
#pragma unroll
        for (int i = 0; i < 8; i++) {
            int id = tid + i * GTH;
            int row = id >> 3, col = (id & 7) * 8;
            cp_async16(&sA[row * LDA2 + col],
                       &A[(size_t)(m0 + row) * F_DIM + k0 + col], true);
        }
#pragma unroll
        for (int i = 0; i < 8; i++) {
            int id = tid + i * GTH;
            int row = id >> 4, col = (id & 15) * 8;
            cp_async16(&sB[row * LDB + col],
                       &W2e[(size_t)(k0 + row) * H_DIM + n0 + col], true);
        }
        CP_COMMIT();
    }

    int buf = 0, nbuf = STAGES - 1;
    for (int kt = 0; kt < NK; kt++) {
        CP_WAIT(1);
        __syncthreads();
        if (kt + 2 < NK) {
            __half* sA = smem + nbuf * STG2;
            __half* sB = sA + BM * LDA2;
            const int k0 = kbase + (kt + 2) * BKH2;
#pragma unroll
            for (int i = 0; i < 8; i++) {
                int id = tid + i * GTH;
                int row = id >> 3, col = (id & 7) * 8;
                cp_async16(&sA[row * LDA2 + col],
                           &A[(size_t)(m0 + row) * F_DIM + k0 + col], true);
            }
#pragma unroll
            for (int i = 0; i < 8; i++) {
                int id = tid + i * GTH;
                int row = id >> 4, col = (id & 15) * 8;
                cp_async16(&sB[row * LDB + col],
                           &W2e[(size_t)(k0 + row) * H_DIM + n0 + col], true);
            }
        }
        CP_COMMIT();
        mma_stage2(smem + buf * STG2, smem + buf * STG2 + BM * LDA2,
                   warp_m, warp_n, fr);
        buf  = (buf  == STAGES - 1) ? 0 : buf + 1;
        nbuf = (nbuf == STAGES - 1) ? 0 : nbuf + 1;
    }
    CP_WAIT0();

    // epilogue: store accumulators to this split's partial buffer
    float* yp = g_yp + (size_t)spl * YP_OFF;
#pragma unroll
    for (int i = 0; i < 4; i++)
#pragma unroll
        for (int j = 0; j < 4; j++)
            wmma::store_matrix_sync(
                &yp[(size_t)(e * CAP + m0 + warp_m * 64 + i * 16) * H_DIM
                    + n0 + warp_n * 64 + j * 16],
                fr.acc[i][j], H_DIM, wmma::mem_row_major);
}

// ---------------- combine: out = residual + sum_e p * (yp0 + yp1) -----------
__global__ void combine_kernel(const float* __restrict__ res,
                               const float* __restrict__ probs,
                               float* __restrict__ out)
{
    int t = blockIdx.x;
    int h = threadIdx.x * 4;
    float4 acc = *reinterpret_cast<const float4*>(&res[(size_t)t * H_DIM + h]);
#pragma unroll
    for (int e = 0; e < E_NUM; e++) {
        float p = probs[t * E_NUM + e];
        if (p > 0.0f) {
            int s = g_slot[t * E_NUM + e];
            float4 y0 = *reinterpret_cast<const float4*>(&g_yp[(size_t)s * H_DIM + h]);
            float4 y1 = *reinterpret_cast<const float4*>(
                &g_yp[YP_OFF + (size_t)s * H_DIM + h]);
            acc.x += p * (y0.x + y1.x);
            acc.y += p * (y0.y + y1.y);
            acc.z += p * (y0.z + y1.z);
            acc.w += p * (y0.w + y1.w);
        }
    }
    *reinterpret_cast<float4*>(&out[(size_t)t * H_DIM + h]) = acc;
}

// ---------------- launcher ---------------------------------------------------
extern "C" void kernel_launch(void* const* d_in, const int* in_sizes, int n_in,
                              void* d_out, int out_size)
{
    const float* x     = (const float*)d_in[0];
    const float* res   = (const float*)d_in[1];
    const float* probs = (const float*)d_in[2];
    const float* w1    = (const float*)d_in[4];
    const float* w2    = (const float*)d_in[5];
    float* out = (float*)d_out;

    (void)cudaFuncSetAttribute(gemm1_kernel,
                               cudaFuncAttributeMaxDynamicSharedMemorySize, SMEM1);
    (void)cudaFuncSetAttribute(gemm2_kernel,
                               cudaFuncAttributeMaxDynamicSharedMemorySize, SMEM2);

    zero_cnt_kernel<<<1, 32>>>();
    prep_kernel<<<8 + 128, NTH>>>(probs, x);
    gemm1_kernel<<<dim3(F_DIM / BN, CAP / BM, E_NUM + 1), NTH, SMEM1>>>(w1, w2);
    gemm2_kernel<<<dim3(H_DIM / BN, CAP / BM, E_NUM * KSPLIT), GTH, SMEM2>>>();
    combine_kernel<<<T_TOK, NTH>>>(res, probs, out);
}